// round 1
// baseline (speedup 1.0000x reference)
#include <cuda_runtime.h>
#include <cuda_bf16.h>
#include <cstdint>

// Problem constants
constexpr int B_ = 2;
constexpr int H_ = 8;
constexpr int N_ = 4096;
constexpr int D_ = 64;
constexpr int DIM_ = 512;
constexpr int INNER_ = H_ * D_;          // 512
constexpr int M_ = B_ * N_;              // 8192 rows for the projections
constexpr float SCALE_ = 0.125f;         // 64^-0.5

// Scratch (device globals: allocation-free rule)
__device__ float g_q[(size_t)B_ * H_ * N_ * D_];     // [B,H,N,D]
__device__ float g_k[(size_t)B_ * H_ * N_ * D_];
__device__ float g_v[(size_t)B_ * H_ * N_ * D_];
__device__ float g_attn[(size_t)B_ * N_ * INNER_];   // [B,N,H*D]

// ---------------------------------------------------------------------------
// Kernel 1: QKV projection.  C[m,e] = sum_k x[m,k] * w_qkv[e,k]
// Tile 128x128x8, 256 threads, 8x8 microtiles. Epilogue scatters into
// g_q/g_k/g_v with [B,H,N,D] layout.
// ---------------------------------------------------------------------------
__global__ __launch_bounds__(256, 2)
void qkv_gemm_kernel(const float* __restrict__ x, const float* __restrict__ w)
{
    __shared__ float As[8][132];
    __shared__ float Bs[8][132];

    const int tid = threadIdx.x;
    const int tx = tid & 15;          // 0..15 -> 8 cols each
    const int ty = tid >> 4;          // 0..15 -> 8 rows each
    const int m0 = blockIdx.y * 128;
    const int e0 = blockIdx.x * 128;

    const int lrow = tid >> 1;        // 0..127
    const int lk   = (tid & 1) * 4;   // 0 or 4

    const float* ag = x + (size_t)(m0 + lrow) * DIM_ + lk;
    const float* bg = w + (size_t)(e0 + lrow) * DIM_ + lk;

    float acc[8][8];
#pragma unroll
    for (int i = 0; i < 8; i++)
#pragma unroll
        for (int j = 0; j < 8; j++) acc[i][j] = 0.f;

    for (int kt = 0; kt < DIM_; kt += 8) {
        float4 av = *(const float4*)(ag + kt);
        float4 bv = *(const float4*)(bg + kt);
        As[lk + 0][lrow] = av.x; As[lk + 1][lrow] = av.y;
        As[lk + 2][lrow] = av.z; As[lk + 3][lrow] = av.w;
        Bs[lk + 0][lrow] = bv.x; Bs[lk + 1][lrow] = bv.y;
        Bs[lk + 2][lrow] = bv.z; Bs[lk + 3][lrow] = bv.w;
        __syncthreads();
#pragma unroll
        for (int kk = 0; kk < 8; kk++) {
            float a[8], b[8];
            *(float4*)(a)     = *(const float4*)&As[kk][ty * 8];
            *(float4*)(a + 4) = *(const float4*)&As[kk][ty * 8 + 4];
            *(float4*)(b)     = *(const float4*)&Bs[kk][tx * 8];
            *(float4*)(b + 4) = *(const float4*)&Bs[kk][tx * 8 + 4];
#pragma unroll
            for (int i = 0; i < 8; i++)
#pragma unroll
                for (int j = 0; j < 8; j++)
                    acc[i][j] = fmaf(a[i], b[j], acc[i][j]);
        }
        __syncthreads();
    }

    // Epilogue: scatter into q/k/v [B,H,N,D]
    const int e_base = e0 + tx * 8;           // 8 consecutive e, same head
    const int which  = e_base >> 9;           // 0=q 1=k 2=v (tile never crosses)
    const int hh     = (e_base >> 6) & 7;
    const int d0     = e_base & 63;           // multiple of 8
    float* dst = (which == 0) ? g_q : (which == 1) ? g_k : g_v;

#pragma unroll
    for (int i = 0; i < 8; i++) {
        const int m = m0 + ty * 8 + i;
        const int bb = m >> 12;
        const int n  = m & 4095;
        float* row = dst + (((size_t)(bb * H_ + hh) * N_) + n) * D_ + d0;
        float4 v0 = make_float4(acc[i][0], acc[i][1], acc[i][2], acc[i][3]);
        float4 v1 = make_float4(acc[i][4], acc[i][5], acc[i][6], acc[i][7]);
        *(float4*)(row)     = v0;
        *(float4*)(row + 4) = v1;
    }
}

// ---------------------------------------------------------------------------
// Kernel 2: fused flash attention (fp32, online softmax).
// Grid: (N/128, B*H). Block: 128 threads.
// Tiles: 128 queries x 64 keys, D=64.
// smem: Qs[64][132] (d-major), Ks[64][68] (d-major), Vs[64][68] (j-major),
//       Ps[64][132] (j-major, transposed P)
// ---------------------------------------------------------------------------
constexpr int QS_LD = 132;
constexpr int KS_LD = 68;
constexpr int VS_LD = 68;
constexpr int PS_LD = 132;
constexpr int ATTN_SMEM_FLOATS = 64 * QS_LD + 64 * KS_LD + 64 * VS_LD + 64 * PS_LD;
constexpr int ATTN_SMEM_BYTES  = ATTN_SMEM_FLOATS * 4;   // 102400

__global__ __launch_bounds__(128, 1)
void attn_kernel()
{
    extern __shared__ float sm[];
    float* Qs = sm;                       // [64][132]  Qs[d][r]
    float* Ks = Qs + 64 * QS_LD;          // [64][68]   Ks[d][j]
    float* Vs = Ks + 64 * KS_LD;          // [64][68]   Vs[j][d]
    float* Ps = Vs + 64 * VS_LD;          // [64][132]  Ps[j][r]

    const int tid = threadIdx.x;
    const int tx = tid & 7;               // 8 col-groups
    const int ty = tid >> 3;              // 16 row-groups
    const int r0 = ty * 8;
    const int c0 = tx * 8;

    const int bh  = blockIdx.y;           // 0..15
    const int qr0 = blockIdx.x * 128;

    const float* Q = g_q + (size_t)bh * N_ * D_;
    const float* K = g_k + (size_t)bh * N_ * D_;
    const float* V = g_v + (size_t)bh * N_ * D_;

    // Load Q tile (scaled), transposed to [d][r]
    for (int idx = tid; idx < 128 * 16; idx += 128) {
        const int r  = idx >> 4;
        const int d4 = (idx & 15) << 2;
        float4 qv = *(const float4*)&Q[(size_t)(qr0 + r) * D_ + d4];
        Qs[(d4 + 0) * QS_LD + r] = qv.x * SCALE_;
        Qs[(d4 + 1) * QS_LD + r] = qv.y * SCALE_;
        Qs[(d4 + 2) * QS_LD + r] = qv.z * SCALE_;
        Qs[(d4 + 3) * QS_LD + r] = qv.w * SCALE_;
    }

    float o[8][8];
#pragma unroll
    for (int i = 0; i < 8; i++)
#pragma unroll
        for (int j = 0; j < 8; j++) o[i][j] = 0.f;
    float mrow[8], lrow[8];
#pragma unroll
    for (int i = 0; i < 8; i++) { mrow[i] = -3.0e38f; lrow[i] = 0.f; }

    for (int jt = 0; jt < N_ / 64; jt++) {
        __syncthreads();   // previous PV done (and Q load on first iter)
        // Load K (transposed to [d][j]) and V ([j][d]) tiles
        for (int idx = tid; idx < 64 * 16; idx += 128) {
            const int j  = idx >> 4;
            const int d4 = (idx & 15) << 2;
            float4 kv = *(const float4*)&K[(size_t)(jt * 64 + j) * D_ + d4];
            Ks[(d4 + 0) * KS_LD + j] = kv.x;
            Ks[(d4 + 1) * KS_LD + j] = kv.y;
            Ks[(d4 + 2) * KS_LD + j] = kv.z;
            Ks[(d4 + 3) * KS_LD + j] = kv.w;
            float4 vv = *(const float4*)&V[(size_t)(jt * 64 + j) * D_ + d4];
            *(float4*)&Vs[j * VS_LD + d4] = vv;
        }
        __syncthreads();

        // GEMM1: S = (Q*scale) @ K^T   (128x64x64)
        float s[8][8];
#pragma unroll
        for (int i = 0; i < 8; i++)
#pragma unroll
            for (int j = 0; j < 8; j++) s[i][j] = 0.f;

#pragma unroll 8
        for (int d = 0; d < 64; d++) {
            float a[8], b[8];
            *(float4*)(a)     = *(const float4*)&Qs[d * QS_LD + r0];
            *(float4*)(a + 4) = *(const float4*)&Qs[d * QS_LD + r0 + 4];
            *(float4*)(b)     = *(const float4*)&Ks[d * KS_LD + c0];
            *(float4*)(b + 4) = *(const float4*)&Ks[d * KS_LD + c0 + 4];
#pragma unroll
            for (int i = 0; i < 8; i++)
#pragma unroll
                for (int j = 0; j < 8; j++)
                    s[i][j] = fmaf(a[i], b[j], s[i][j]);
        }

        // Online softmax (rows owned by the 8 tx-siblings; butterfly over tx)
#pragma unroll
        for (int i = 0; i < 8; i++) {
            float tm = s[i][0];
#pragma unroll
            for (int j = 1; j < 8; j++) tm = fmaxf(tm, s[i][j]);
            tm = fmaxf(tm, __shfl_xor_sync(0xffffffffu, tm, 1));
            tm = fmaxf(tm, __shfl_xor_sync(0xffffffffu, tm, 2));
            tm = fmaxf(tm, __shfl_xor_sync(0xffffffffu, tm, 4));
            const float mnew = fmaxf(mrow[i], tm);
            const float alpha = __expf(mrow[i] - mnew);
            float rs = 0.f;
#pragma unroll
            for (int j = 0; j < 8; j++) {
                const float p = __expf(s[i][j] - mnew);
                s[i][j] = p;
                rs += p;
            }
            rs += __shfl_xor_sync(0xffffffffu, rs, 1);
            rs += __shfl_xor_sync(0xffffffffu, rs, 2);
            rs += __shfl_xor_sync(0xffffffffu, rs, 4);
            lrow[i] = lrow[i] * alpha + rs;
            mrow[i] = mnew;
#pragma unroll
            for (int d8 = 0; d8 < 8; d8++) o[i][d8] *= alpha;
        }

        // Store P transposed: Ps[j][r] (column-vectorized STS.128)
#pragma unroll
        for (int jj = 0; jj < 8; jj++) {
            float4 p0 = make_float4(s[0][jj], s[1][jj], s[2][jj], s[3][jj]);
            float4 p1 = make_float4(s[4][jj], s[5][jj], s[6][jj], s[7][jj]);
            *(float4*)&Ps[(c0 + jj) * PS_LD + r0]     = p0;
            *(float4*)&Ps[(c0 + jj) * PS_LD + r0 + 4] = p1;
        }
        __syncthreads();

        // GEMM2: O += P @ V   (128x64x64), cols of O are d = c0..c0+7
#pragma unroll 8
        for (int j = 0; j < 64; j++) {
            float a[8], b[8];
            *(float4*)(a)     = *(const float4*)&Ps[j * PS_LD + r0];
            *(float4*)(a + 4) = *(const float4*)&Ps[j * PS_LD + r0 + 4];
            *(float4*)(b)     = *(const float4*)&Vs[j * VS_LD + c0];
            *(float4*)(b + 4) = *(const float4*)&Vs[j * VS_LD + c0 + 4];
#pragma unroll
            for (int i = 0; i < 8; i++)
#pragma unroll
                for (int d8 = 0; d8 < 8; d8++)
                    o[i][d8] = fmaf(a[i], b[d8], o[i][d8]);
        }
    }

    // Epilogue: normalize and write to g_attn [B,N,H*D]
    const int bb = bh >> 3;
    const int hh = bh & 7;
#pragma unroll
    for (int i = 0; i < 8; i++) {
        const float inv = 1.f / lrow[i];
        const int n = qr0 + r0 + i;
        float* row = g_attn + ((size_t)(bb * N_ + n)) * INNER_ + hh * D_ + c0;
        float4 v0 = make_float4(o[i][0] * inv, o[i][1] * inv, o[i][2] * inv, o[i][3] * inv);
        float4 v1 = make_float4(o[i][4] * inv, o[i][5] * inv, o[i][6] * inv, o[i][7] * inv);
        *(float4*)(row)     = v0;
        *(float4*)(row + 4) = v1;
    }
}

// ---------------------------------------------------------------------------
// Kernel 3: output projection.  out[m,d] = sum_e attn[m,e]*w_out[d,e] + b_out[d]
// ---------------------------------------------------------------------------
__global__ __launch_bounds__(256, 2)
void proj_gemm_kernel(const float* __restrict__ w, const float* __restrict__ bias,
                      float* __restrict__ out)
{
    __shared__ float As[8][132];
    __shared__ float Bs[8][132];

    const int tid = threadIdx.x;
    const int tx = tid & 15;
    const int ty = tid >> 4;
    const int m0 = blockIdx.y * 128;
    const int n0 = blockIdx.x * 128;

    const int lrow = tid >> 1;
    const int lk   = (tid & 1) * 4;

    const float* ag = g_attn + (size_t)(m0 + lrow) * INNER_ + lk;
    const float* bg = w + (size_t)(n0 + lrow) * INNER_ + lk;

    float acc[8][8];
#pragma unroll
    for (int i = 0; i < 8; i++)
#pragma unroll
        for (int j = 0; j < 8; j++) acc[i][j] = 0.f;

    for (int kt = 0; kt < INNER_; kt += 8) {
        float4 av = *(const float4*)(ag + kt);
        float4 bv = *(const float4*)(bg + kt);
        As[lk + 0][lrow] = av.x; As[lk + 1][lrow] = av.y;
        As[lk + 2][lrow] = av.z; As[lk + 3][lrow] = av.w;
        Bs[lk + 0][lrow] = bv.x; Bs[lk + 1][lrow] = bv.y;
        Bs[lk + 2][lrow] = bv.z; Bs[lk + 3][lrow] = bv.w;
        __syncthreads();
#pragma unroll
        for (int kk = 0; kk < 8; kk++) {
            float a[8], b[8];
            *(float4*)(a)     = *(const float4*)&As[kk][ty * 8];
            *(float4*)(a + 4) = *(const float4*)&As[kk][ty * 8 + 4];
            *(float4*)(b)     = *(const float4*)&Bs[kk][tx * 8];
            *(float4*)(b + 4) = *(const float4*)&Bs[kk][tx * 8 + 4];
#pragma unroll
            for (int i = 0; i < 8; i++)
#pragma unroll
                for (int j = 0; j < 8; j++)
                    acc[i][j] = fmaf(a[i], b[j], acc[i][j]);
        }
        __syncthreads();
    }

    const int col = n0 + tx * 8;
    float4 bv0 = *(const float4*)&bias[col];
    float4 bv1 = *(const float4*)&bias[col + 4];
#pragma unroll
    for (int i = 0; i < 8; i++) {
        const int m = m0 + ty * 8 + i;
        float* row = out + (size_t)m * DIM_ + col;
        float4 v0 = make_float4(acc[i][0] + bv0.x, acc[i][1] + bv0.y,
                                acc[i][2] + bv0.z, acc[i][3] + bv0.w);
        float4 v1 = make_float4(acc[i][4] + bv1.x, acc[i][5] + bv1.y,
                                acc[i][6] + bv1.z, acc[i][7] + bv1.w);
        *(float4*)(row)     = v0;
        *(float4*)(row + 4) = v1;
    }
}

// ---------------------------------------------------------------------------
extern "C" void kernel_launch(void* const* d_in, const int* in_sizes, int n_in,
                              void* d_out, int out_size)
{
    const float* x      = (const float*)d_in[0];   // [2,4096,512]
    const float* w_qkv  = (const float*)d_in[1];   // [1536,512]
    const float* w_out  = (const float*)d_in[2];   // [512,512]
    const float* b_out  = (const float*)d_in[3];   // [512]
    float* out = (float*)d_out;                    // [2,4096,512]

    // QKV projection: grid (1536/128, 8192/128)
    qkv_gemm_kernel<<<dim3(12, 64), 256>>>(x, w_qkv);

    // Attention: grid (4096/128, B*H)
    cudaFuncSetAttribute(attn_kernel,
                         cudaFuncAttributeMaxDynamicSharedMemorySize,
                         ATTN_SMEM_BYTES);
    attn_kernel<<<dim3(N_ / 128, B_ * H_), 128, ATTN_SMEM_BYTES>>>();

    // Output projection: grid (512/128, 8192/128)
    proj_gemm_kernel<<<dim3(4, 64), 256>>>(w_out, b_out, out);
}

// round 2
// speedup vs baseline: 1.4832x; 1.4832x over previous
#include <cuda_runtime.h>
#include <cuda_bf16.h>
#include <cstdint>

// Problem constants
constexpr int B_ = 2;
constexpr int H_ = 8;
constexpr int N_ = 4096;
constexpr int D_ = 64;
constexpr int DIM_ = 512;
constexpr int INNER_ = H_ * D_;          // 512
constexpr float SCALE_ = 0.125f;         // 64^-0.5

// Scratch (device globals: allocation-free rule)
__device__ float g_q[(size_t)B_ * H_ * N_ * D_];     // [B,H,N,D]
__device__ float g_k[(size_t)B_ * H_ * N_ * D_];
__device__ float g_v[(size_t)B_ * H_ * N_ * D_];
__device__ float g_attn[(size_t)B_ * N_ * INNER_];   // [B,N,H*D]

// ---------------------------------------------------------------------------
// tf32 helpers
// ---------------------------------------------------------------------------
__device__ __forceinline__ float tf32r(float x) {
    uint32_t u;
    asm("cvt.rna.tf32.f32 %0, %1;" : "=r"(u) : "f"(x));
    return __uint_as_float(u);
}

__device__ __forceinline__ void mma_tf32(float* c, const uint32_t* a,
                                         uint32_t b0, uint32_t b1) {
    asm volatile(
        "mma.sync.aligned.m16n8k8.row.col.f32.tf32.tf32.f32 "
        "{%0,%1,%2,%3}, {%4,%5,%6,%7}, {%8,%9}, {%0,%1,%2,%3};\n"
        : "+f"(c[0]), "+f"(c[1]), "+f"(c[2]), "+f"(c[3])
        : "r"(a[0]), "r"(a[1]), "r"(a[2]), "r"(a[3]), "r"(b0), "r"(b1));
}

// ---------------------------------------------------------------------------
// Kernel 1: QKV projection (fp32 FFMA, unchanged — at FFMA roofline)
// ---------------------------------------------------------------------------
__global__ __launch_bounds__(256, 2)
void qkv_gemm_kernel(const float* __restrict__ x, const float* __restrict__ w)
{
    __shared__ float As[8][132];
    __shared__ float Bs[8][132];

    const int tid = threadIdx.x;
    const int tx = tid & 15;
    const int ty = tid >> 4;
    const int m0 = blockIdx.y * 128;
    const int e0 = blockIdx.x * 128;

    const int lrow = tid >> 1;
    const int lk   = (tid & 1) * 4;

    const float* ag = x + (size_t)(m0 + lrow) * DIM_ + lk;
    const float* bg = w + (size_t)(e0 + lrow) * DIM_ + lk;

    float acc[8][8];
#pragma unroll
    for (int i = 0; i < 8; i++)
#pragma unroll
        for (int j = 0; j < 8; j++) acc[i][j] = 0.f;

    for (int kt = 0; kt < DIM_; kt += 8) {
        float4 av = *(const float4*)(ag + kt);
        float4 bv = *(const float4*)(bg + kt);
        As[lk + 0][lrow] = av.x; As[lk + 1][lrow] = av.y;
        As[lk + 2][lrow] = av.z; As[lk + 3][lrow] = av.w;
        Bs[lk + 0][lrow] = bv.x; Bs[lk + 1][lrow] = bv.y;
        Bs[lk + 2][lrow] = bv.z; Bs[lk + 3][lrow] = bv.w;
        __syncthreads();
#pragma unroll
        for (int kk = 0; kk < 8; kk++) {
            float a[8], b[8];
            *(float4*)(a)     = *(const float4*)&As[kk][ty * 8];
            *(float4*)(a + 4) = *(const float4*)&As[kk][ty * 8 + 4];
            *(float4*)(b)     = *(const float4*)&Bs[kk][tx * 8];
            *(float4*)(b + 4) = *(const float4*)&Bs[kk][tx * 8 + 4];
#pragma unroll
            for (int i = 0; i < 8; i++)
#pragma unroll
                for (int j = 0; j < 8; j++)
                    acc[i][j] = fmaf(a[i], b[j], acc[i][j]);
        }
        __syncthreads();
    }

    const int e_base = e0 + tx * 8;
    const int which  = e_base >> 9;
    const int hh     = (e_base >> 6) & 7;
    const int d0     = e_base & 63;
    float* dst = (which == 0) ? g_q : (which == 1) ? g_k : g_v;

#pragma unroll
    for (int i = 0; i < 8; i++) {
        const int m = m0 + ty * 8 + i;
        const int bb = m >> 12;
        const int n  = m & 4095;
        float* row = dst + (((size_t)(bb * H_ + hh) * N_) + n) * D_ + d0;
        float4 v0 = make_float4(acc[i][0], acc[i][1], acc[i][2], acc[i][3]);
        float4 v1 = make_float4(acc[i][4], acc[i][5], acc[i][6], acc[i][7]);
        *(float4*)(row)     = v0;
        *(float4*)(row + 4) = v1;
    }
}

// ---------------------------------------------------------------------------
// Kernel 2: fused flash attention with tf32 mma.sync tensor cores.
// Grid (32, 16), 128 threads (4 warps). Each warp owns 32 query rows.
// Key tiles of 64. Smem layouts are permuted for vectorized fragment loads:
//   A-operand perm:  col c   -> (c&3)*16 + (c>>3)*2 + ((c>>2)&1)
//   B-operand perm:  col n   -> (n&7)*8  + (n>>3)
// ---------------------------------------------------------------------------
constexpr int LD2 = 68;   // padded row stride (floats), 16B-aligned rows
constexpr int ATTN2_SMEM = (128 + 64 + 64 + 128) * LD2 * 4;   // 104448 B

__global__ __launch_bounds__(128, 1)
void attn_tc_kernel()
{
    extern __shared__ float sm2[];
    float* Qp = sm2;                  // [128][LD2]  A-perm (scaled, tf32)
    float* Kp = Qp + 128 * LD2;       // [64][LD2]   Kp[d][perm_b(j)]
    float* Vp = Kp + 64 * LD2;        // [64][LD2]   Vp[j][perm_b(d)]
    float* Pp = Vp + 64 * LD2;        // [128][LD2]  A-perm

    const int tid  = threadIdx.x;
    const int w    = tid >> 5;
    const int lane = tid & 31;
    const int g    = lane >> 2;       // 0..7
    const int q    = lane & 3;        // 0..3

    const int bh  = blockIdx.y;
    const int qr0 = blockIdx.x * 128;

    const float* Q = g_q + (size_t)bh * N_ * D_;
    const float* K = g_k + (size_t)bh * N_ * D_;
    const float* V = g_v + (size_t)bh * N_ * D_;

    // ---- Load Q tile (scale + tf32 round + A-perm). One row per thread. ----
    {
        const float* qrow = Q + (size_t)(qr0 + tid) * D_;
        float* dst = Qp + tid * LD2;
#pragma unroll
        for (int c4 = 0; c4 < 64; c4 += 4) {
            float4 v = *(const float4*)(qrow + c4);
            const int base = ((c4 >> 3) << 1) + ((c4 >> 2) & 1);
            dst[0 * 16 + base] = tf32r(v.x * SCALE_);
            dst[1 * 16 + base] = tf32r(v.y * SCALE_);
            dst[2 * 16 + base] = tf32r(v.z * SCALE_);
            dst[3 * 16 + base] = tf32r(v.w * SCALE_);
        }
    }

    // Running stats / accumulators. Row slots: (mt, h) -> row w*32+mt*16+g+8h
    float o[2][8][4];
#pragma unroll
    for (int mt = 0; mt < 2; mt++)
#pragma unroll
        for (int nt = 0; nt < 8; nt++)
#pragma unroll
            for (int e = 0; e < 4; e++) o[mt][nt][e] = 0.f;
    float m_run[2][2], l_run[2][2];
#pragma unroll
    for (int mt = 0; mt < 2; mt++)
#pragma unroll
        for (int h = 0; h < 2; h++) { m_run[mt][h] = -1e30f; l_run[mt][h] = 0.f; }

    const int r0 = w * 32;
    const int jl   = tid & 63;        // key row this thread loads
    const int halfc = (tid >> 6) * 32; // col half
    const int jp   = (jl & 7) * 8 + (jl >> 3);

    for (int jt = 0; jt < N_ / 64; jt++) {
        __syncthreads();   // Kp/Vp/Pp free

        // ---- Load K,V tile -> permuted smem (tf32-rounded) ----
        {
            const float* krow = K + (size_t)(jt * 64 + jl) * D_ + halfc;
            const float* vrow = V + (size_t)(jt * 64 + jl) * D_ + halfc;
            float* vdstbase = Vp + jl * LD2;
#pragma unroll
            for (int c4 = 0; c4 < 32; c4 += 4) {
                const int c = halfc + c4;
                float4 kv = *(const float4*)(krow + c4);
                Kp[(c + 0) * LD2 + jp] = tf32r(kv.x);
                Kp[(c + 1) * LD2 + jp] = tf32r(kv.y);
                Kp[(c + 2) * LD2 + jp] = tf32r(kv.z);
                Kp[(c + 3) * LD2 + jp] = tf32r(kv.w);
                float4 vv = *(const float4*)(vrow + c4);
                float* vdst = vdstbase + (c >> 3);
                vdst[((c + 0) & 7) * 8] = tf32r(vv.x);
                vdst[((c + 1) & 7) * 8] = tf32r(vv.y);
                vdst[((c + 2) & 7) * 8] = tf32r(vv.z);
                vdst[((c + 3) & 7) * 8] = tf32r(vv.w);
            }
        }
        __syncthreads();

        // ---- GEMM1: S = Qs @ K^T  (warp: 32 x 64, K=64) ----
        float s[2][8][4];
#pragma unroll
        for (int mt = 0; mt < 2; mt++)
#pragma unroll
            for (int nt = 0; nt < 8; nt++)
#pragma unroll
                for (int e = 0; e < 4; e++) s[mt][nt][e] = 0.f;

#pragma unroll
        for (int kc = 0; kc < 8; kc++) {
            uint32_t a[2][4];
#pragma unroll
            for (int mt = 0; mt < 2; mt++) {
                const float* arow = Qp + (r0 + mt * 16 + g) * LD2 + q * 16 + kc * 2;
                float2 alo = *(const float2*)arow;
                float2 ahi = *(const float2*)(arow + 8 * LD2);
                a[mt][0] = __float_as_uint(alo.x);
                a[mt][1] = __float_as_uint(ahi.x);
                a[mt][2] = __float_as_uint(alo.y);
                a[mt][3] = __float_as_uint(ahi.y);
            }
            const float* brow = Kp + (kc * 8 + q) * LD2 + g * 8;
            float4 bl0 = *(const float4*)(brow);
            float4 bl1 = *(const float4*)(brow + 4);
            float4 bh0 = *(const float4*)(brow + 4 * LD2);
            float4 bh1 = *(const float4*)(brow + 4 * LD2 + 4);
            const float blv[8] = {bl0.x, bl0.y, bl0.z, bl0.w, bl1.x, bl1.y, bl1.z, bl1.w};
            const float bhv[8] = {bh0.x, bh0.y, bh0.z, bh0.w, bh1.x, bh1.y, bh1.z, bh1.w};
#pragma unroll
            for (int nt = 0; nt < 8; nt++) {
                const uint32_t b0 = __float_as_uint(blv[nt]);
                const uint32_t b1 = __float_as_uint(bhv[nt]);
                mma_tf32(s[0][nt], a[0], b0, b1);
                mma_tf32(s[1][nt], a[1], b0, b1);
            }
        }

        // ---- Online softmax (rows warp-local; quad reduce over q lanes) ----
#pragma unroll
        for (int mt = 0; mt < 2; mt++) {
#pragma unroll
            for (int h = 0; h < 2; h++) {
                float mloc = -1e30f;
#pragma unroll
                for (int nt = 0; nt < 8; nt++)
                    mloc = fmaxf(mloc, fmaxf(s[mt][nt][2 * h], s[mt][nt][2 * h + 1]));
                mloc = fmaxf(mloc, __shfl_xor_sync(0xffffffffu, mloc, 1));
                mloc = fmaxf(mloc, __shfl_xor_sync(0xffffffffu, mloc, 2));
                const float mnew  = fmaxf(m_run[mt][h], mloc);
                const float alpha = __expf(m_run[mt][h] - mnew);
                float rs = 0.f;
#pragma unroll
                for (int nt = 0; nt < 8; nt++) {
                    const float p0 = __expf(s[mt][nt][2 * h]     - mnew);
                    const float p1 = __expf(s[mt][nt][2 * h + 1] - mnew);
                    s[mt][nt][2 * h]     = p0;
                    s[mt][nt][2 * h + 1] = p1;
                    rs += p0 + p1;
                }
                rs += __shfl_xor_sync(0xffffffffu, rs, 1);
                rs += __shfl_xor_sync(0xffffffffu, rs, 2);
                l_run[mt][h] = l_run[mt][h] * alpha + rs;
                m_run[mt][h] = mnew;
#pragma unroll
                for (int nt = 0; nt < 8; nt++) {
                    o[mt][nt][2 * h]     *= alpha;
                    o[mt][nt][2 * h + 1] *= alpha;
                }
            }
        }

        // ---- Store P (tf32, A-perm layout) ----
        {
            const int pos0 = ((2 * q) & 3) * 16 + (q >> 1);
#pragma unroll
            for (int mt = 0; mt < 2; mt++) {
                float* prow0 = Pp + (r0 + mt * 16 + g) * LD2;
                float* prow1 = prow0 + 8 * LD2;
#pragma unroll
                for (int nt = 0; nt < 8; nt++) {
                    prow0[pos0 + nt * 2]      = tf32r(s[mt][nt][0]);
                    prow0[pos0 + 16 + nt * 2] = tf32r(s[mt][nt][1]);
                    prow1[pos0 + nt * 2]      = tf32r(s[mt][nt][2]);
                    prow1[pos0 + 16 + nt * 2] = tf32r(s[mt][nt][3]);
                }
            }
        }
        __syncthreads();

        // ---- GEMM2: O += P @ V  (warp: 32 x 64, K=64) ----
#pragma unroll
        for (int kc = 0; kc < 8; kc++) {
            uint32_t a[2][4];
#pragma unroll
            for (int mt = 0; mt < 2; mt++) {
                const float* arow = Pp + (r0 + mt * 16 + g) * LD2 + q * 16 + kc * 2;
                float2 alo = *(const float2*)arow;
                float2 ahi = *(const float2*)(arow + 8 * LD2);
                a[mt][0] = __float_as_uint(alo.x);
                a[mt][1] = __float_as_uint(ahi.x);
                a[mt][2] = __float_as_uint(alo.y);
                a[mt][3] = __float_as_uint(ahi.y);
            }
            const float* brow = Vp + (kc * 8 + q) * LD2 + g * 8;
            float4 bl0 = *(const float4*)(brow);
            float4 bl1 = *(const float4*)(brow + 4);
            float4 bh0 = *(const float4*)(brow + 4 * LD2);
            float4 bh1 = *(const float4*)(brow + 4 * LD2 + 4);
            const float blv[8] = {bl0.x, bl0.y, bl0.z, bl0.w, bl1.x, bl1.y, bl1.z, bl1.w};
            const float bhv[8] = {bh0.x, bh0.y, bh0.z, bh0.w, bh1.x, bh1.y, bh1.z, bh1.w};
#pragma unroll
            for (int nt = 0; nt < 8; nt++) {
                const uint32_t b0 = __float_as_uint(blv[nt]);
                const uint32_t b1 = __float_as_uint(bhv[nt]);
                mma_tf32(o[0][nt], a[0], b0, b1);
                mma_tf32(o[1][nt], a[1], b0, b1);
            }
        }
    }

    // ---- Epilogue: normalize, write to g_attn [B,N,H*D] ----
    const int bb = bh >> 3;
    const int hh = bh & 7;
#pragma unroll
    for (int mt = 0; mt < 2; mt++) {
#pragma unroll
        for (int h = 0; h < 2; h++) {
            const float inv = 1.f / l_run[mt][h];
            const int n = qr0 + r0 + mt * 16 + g + 8 * h;
            float* row = g_attn + ((size_t)(bb * N_ + n)) * INNER_ + hh * 64 + 2 * q;
#pragma unroll
            for (int nt = 0; nt < 8; nt++) {
                float2 val;
                val.x = o[mt][nt][2 * h]     * inv;
                val.y = o[mt][nt][2 * h + 1] * inv;
                *(float2*)(row + nt * 8) = val;
            }
        }
    }
}

// ---------------------------------------------------------------------------
// Kernel 3: output projection (fp32 FFMA, unchanged)
// ---------------------------------------------------------------------------
__global__ __launch_bounds__(256, 2)
void proj_gemm_kernel(const float* __restrict__ w, const float* __restrict__ bias,
                      float* __restrict__ out)
{
    __shared__ float As[8][132];
    __shared__ float Bs[8][132];

    const int tid = threadIdx.x;
    const int tx = tid & 15;
    const int ty = tid >> 4;
    const int m0 = blockIdx.y * 128;
    const int n0 = blockIdx.x * 128;

    const int lrow = tid >> 1;
    const int lk   = (tid & 1) * 4;

    const float* ag = g_attn + (size_t)(m0 + lrow) * INNER_ + lk;
    const float* bg = w + (size_t)(n0 + lrow) * INNER_ + lk;

    float acc[8][8];
#pragma unroll
    for (int i = 0; i < 8; i++)
#pragma unroll
        for (int j = 0; j < 8; j++) acc[i][j] = 0.f;

    for (int kt = 0; kt < INNER_; kt += 8) {
        float4 av = *(const float4*)(ag + kt);
        float4 bv = *(const float4*)(bg + kt);
        As[lk + 0][lrow] = av.x; As[lk + 1][lrow] = av.y;
        As[lk + 2][lrow] = av.z; As[lk + 3][lrow] = av.w;
        Bs[lk + 0][lrow] = bv.x; Bs[lk + 1][lrow] = bv.y;
        Bs[lk + 2][lrow] = bv.z; Bs[lk + 3][lrow] = bv.w;
        __syncthreads();
#pragma unroll
        for (int kk = 0; kk < 8; kk++) {
            float a[8], b[8];
            *(float4*)(a)     = *(const float4*)&As[kk][ty * 8];
            *(float4*)(a + 4) = *(const float4*)&As[kk][ty * 8 + 4];
            *(float4*)(b)     = *(const float4*)&Bs[kk][tx * 8];
            *(float4*)(b + 4) = *(const float4*)&Bs[kk][tx * 8 + 4];
#pragma unroll
            for (int i = 0; i < 8; i++)
#pragma unroll
                for (int j = 0; j < 8; j++)
                    acc[i][j] = fmaf(a[i], b[j], acc[i][j]);
        }
        __syncthreads();
    }

    const int col = n0 + tx * 8;
    float4 bv0 = *(const float4*)&bias[col];
    float4 bv1 = *(const float4*)&bias[col + 4];
#pragma unroll
    for (int i = 0; i < 8; i++) {
        const int m = m0 + ty * 8 + i;
        float* row = out + (size_t)m * DIM_ + col;
        float4 v0 = make_float4(acc[i][0] + bv0.x, acc[i][1] + bv0.y,
                                acc[i][2] + bv0.z, acc[i][3] + bv0.w);
        float4 v1 = make_float4(acc[i][4] + bv1.x, acc[i][5] + bv1.y,
                                acc[i][6] + bv1.z, acc[i][7] + bv1.w);
        *(float4*)(row)     = v0;
        *(float4*)(row + 4) = v1;
    }
}

// ---------------------------------------------------------------------------
extern "C" void kernel_launch(void* const* d_in, const int* in_sizes, int n_in,
                              void* d_out, int out_size)
{
    const float* x      = (const float*)d_in[0];   // [2,4096,512]
    const float* w_qkv  = (const float*)d_in[1];   // [1536,512]
    const float* w_out  = (const float*)d_in[2];   // [512,512]
    const float* b_out  = (const float*)d_in[3];   // [512]
    float* out = (float*)d_out;                    // [2,4096,512]

    qkv_gemm_kernel<<<dim3(12, 64), 256>>>(x, w_qkv);

    cudaFuncSetAttribute(attn_tc_kernel,
                         cudaFuncAttributeMaxDynamicSharedMemorySize,
                         ATTN2_SMEM);
    attn_tc_kernel<<<dim3(N_ / 128, B_ * H_), 128, ATTN2_SMEM>>>();

    proj_gemm_kernel<<<dim3(4, 64), 256>>>(w_out, b_out, out);
}